// round 6
// baseline (speedup 1.0000x reference)
#include <cuda_runtime.h>
#include <cuda_bf16.h>
#include <math.h>

#define D_MODEL   1024
#define NUM_HEADS 16
#define HEAD_DIM  64
#define BATCH     2
#define SEQ       2048
#define NROWS     (BATCH * SEQ)   // 4096

// ---------------------------------------------------------------------------
// Scratch (device globals; no runtime allocation allowed)
// ---------------------------------------------------------------------------
__device__ float g_Q [(size_t)NROWS * D_MODEL];
__device__ float g_K [(size_t)NROWS * D_MODEL];
__device__ float g_V [(size_t)NROWS * D_MODEL];
__device__ float g_AO[(size_t)NROWS * D_MODEL];
__device__ float g_m [(size_t)BATCH * NUM_HEADS * SEQ];
__device__ float g_l [(size_t)BATCH * NUM_HEADS * SEQ];

__device__ __forceinline__ float* scratch_ptr(int sel) {
    switch (sel) {
        case 0: return g_Q;
        case 1: return g_K;
        case 2: return g_V;
        default: return g_AO;
    }
}

// ---------------------------------------------------------------------------
// SGEMM: C[M,N] = A[M,K] @ W[K,N] + bias[N]
// 128x128 block tile, BK=8, 256 threads, 8x8 microtile per thread.
// ---------------------------------------------------------------------------
__global__ __launch_bounds__(256)
void sgemm_bias_kernel(const float* A, int aSel,
                       const float* W,
                       const float* bias,
                       float* C, int cSel,
                       int M, int N, int K)
{
    if (aSel >= 0) A = scratch_ptr(aSel);
    if (cSel >= 0) C = scratch_ptr(cSel);

    __shared__ float As[8][128];   // [k][m] (transposed)
    __shared__ float Bs[8][128];   // [k][n]

    const int tid = threadIdx.x;
    const int tx  = tid & 15;
    const int ty  = tid >> 4;

    const int rowBase = blockIdx.y * 128;
    const int colBase = blockIdx.x * 128;

    const int aRow = tid >> 1;
    const int aCol = (tid & 1) * 4;
    const int bRow = tid >> 5;
    const int bCol = (tid & 31) * 4;

    const float* Aptr = A + (size_t)(rowBase + aRow) * K + aCol;
    const float* Wptr = W + (size_t)bRow * N + colBase + bCol;

    float acc[8][8];
#pragma unroll
    for (int i = 0; i < 8; i++)
#pragma unroll
        for (int j = 0; j < 8; j++) acc[i][j] = 0.f;

    for (int k0 = 0; k0 < K; k0 += 8) {
        float4 av = *(const float4*)(Aptr + k0);
        float4 bv = *(const float4*)(Wptr + (size_t)k0 * N);

        __syncthreads();
        As[aCol + 0][aRow] = av.x;
        As[aCol + 1][aRow] = av.y;
        As[aCol + 2][aRow] = av.z;
        As[aCol + 3][aRow] = av.w;
        *(float4*)&Bs[bRow][bCol] = bv;
        __syncthreads();

#pragma unroll
        for (int kk = 0; kk < 8; kk++) {
            float4 a0 = *(const float4*)&As[kk][ty * 4];
            float4 a1 = *(const float4*)&As[kk][64 + ty * 4];
            float4 b0 = *(const float4*)&Bs[kk][tx * 4];
            float4 b1 = *(const float4*)&Bs[kk][64 + tx * 4];
            float ar[8] = {a0.x, a0.y, a0.z, a0.w, a1.x, a1.y, a1.z, a1.w};
            float br[8] = {b0.x, b0.y, b0.z, b0.w, b1.x, b1.y, b1.z, b1.w};
#pragma unroll
            for (int i = 0; i < 8; i++)
#pragma unroll
                for (int j = 0; j < 8; j++)
                    acc[i][j] = fmaf(ar[i], br[j], acc[i][j]);
        }
    }

    float4 bs0 = *(const float4*)&bias[colBase + tx * 4];
    float4 bs1 = *(const float4*)&bias[colBase + 64 + tx * 4];
    const float bb0[4] = {bs0.x, bs0.y, bs0.z, bs0.w};
    const float bb1[4] = {bs1.x, bs1.y, bs1.z, bs1.w};

#pragma unroll
    for (int i = 0; i < 8; i++) {
        int r = rowBase + ((i < 4) ? (ty * 4 + i) : (64 + ty * 4 + (i - 4)));
        float4 v0, v1;
        v0.x = acc[i][0] + bb0[0]; v0.y = acc[i][1] + bb0[1];
        v0.z = acc[i][2] + bb0[2]; v0.w = acc[i][3] + bb0[3];
        v1.x = acc[i][4] + bb1[0]; v1.y = acc[i][5] + bb1[1];
        v1.z = acc[i][6] + bb1[2]; v1.w = acc[i][7] + bb1[3];
        *(float4*)&C[(size_t)r * N + colBase + tx * 4]      = v0;
        *(float4*)&C[(size_t)r * N + colBase + 64 + tx * 4] = v1;
    }
}

// ---------------------------------------------------------------------------
// Attention pass 1: per (b, h, 128-row Q tile), 256 threads, 8x8 microtile.
// Computes raw scaled+masked scores -> attnW (scratch region == final output
// region), exact online (m, l) per row -> g_m / g_l.
// Q/K staged transposed [d][*] in d-chunks of 32.
// ---------------------------------------------------------------------------
__global__ __launch_bounds__(256)
void attn_pass1_kernel(const int* __restrict__ mask, float* __restrict__ attnW)
{
    const int qt  = blockIdx.x;     // 0..15
    const int h   = blockIdx.y;
    const int b   = blockIdx.z;
    const int tid = threadIdx.x;
    const int tx  = tid & 15;
    const int ty  = tid >> 4;

    __shared__ float smQ[32][132];  // [d][q]
    __shared__ float smK[32][132];  // [d][k]
    __shared__ int   maskS[128];

    const int q0 = qt * 128;

    int qr[8];
#pragma unroll
    for (int i = 0; i < 8; i++)
        qr[i] = (i < 4) ? (ty * 4 + i) : (64 + ty * 4 + (i - 4));

    float m[8], l[8];
#pragma unroll
    for (int i = 0; i < 8; i++) { m[i] = -3.0e38f; l[i] = 0.f; }

    const size_t attnRowBase = (size_t)(b * NUM_HEADS + h) * SEQ + q0;

    for (int ks = 0; ks < SEQ; ks += 128) {
        float s[8][8];
#pragma unroll
        for (int i = 0; i < 8; i++)
#pragma unroll
            for (int j = 0; j < 8; j++) s[i][j] = 0.f;

#pragma unroll
        for (int dc = 0; dc < 64; dc += 32) {
            __syncthreads();
            if (dc == 0 && tid < 128) maskS[tid] = mask[b * SEQ + ks + tid];
            // load Q and K chunks, transposed into [d][row]
#pragma unroll
            for (int u = 0; u < 4; u++) {
                int lin = tid + u * 256;
                int r   = lin >> 3;          // 0..127
                int dl  = (lin & 7) * 4;     // 0..28
                float4 v = *(const float4*)&g_Q[(size_t)(b * SEQ + q0 + r) * D_MODEL
                                                + h * HEAD_DIM + dc + dl];
                smQ[dl + 0][r] = v.x; smQ[dl + 1][r] = v.y;
                smQ[dl + 2][r] = v.z; smQ[dl + 3][r] = v.w;
                float4 w = *(const float4*)&g_K[(size_t)(b * SEQ + ks + r) * D_MODEL
                                                + h * HEAD_DIM + dc + dl];
                smK[dl + 0][r] = w.x; smK[dl + 1][r] = w.y;
                smK[dl + 2][r] = w.z; smK[dl + 3][r] = w.w;
            }
            __syncthreads();

#pragma unroll 4
            for (int kk = 0; kk < 32; kk++) {
                float4 a0 = *(const float4*)&smQ[kk][ty * 4];
                float4 a1 = *(const float4*)&smQ[kk][64 + ty * 4];
                float4 b0 = *(const float4*)&smK[kk][tx * 4];
                float4 b1 = *(const float4*)&smK[kk][64 + tx * 4];
                float ar[8] = {a0.x, a0.y, a0.z, a0.w, a1.x, a1.y, a1.z, a1.w};
                float br[8] = {b0.x, b0.y, b0.z, b0.w, b1.x, b1.y, b1.z, b1.w};
#pragma unroll
                for (int i = 0; i < 8; i++)
#pragma unroll
                    for (int j = 0; j < 8; j++)
                        s[i][j] = fmaf(ar[i], br[j], s[i][j]);
            }
        }

        // scale 1/sqrt(64), apply mask
#pragma unroll
        for (int j = 0; j < 8; j++) {
            int jcol = (j < 4) ? (tx * 4 + j) : (64 + tx * 4 + (j - 4));
            bool masked = (maskS[jcol] == 0);
#pragma unroll
            for (int i = 0; i < 8; i++) {
                float sv = s[i][j] * 0.125f;
                s[i][j] = masked ? -3.0e38f : sv;
            }
        }

        // write raw scores (scratch in the output region; finalized in pass 2)
#pragma unroll
        for (int i = 0; i < 8; i++) {
            size_t base = (attnRowBase + qr[i]) * SEQ + ks;
            *(float4*)&attnW[base + tx * 4]      = make_float4(s[i][0], s[i][1], s[i][2], s[i][3]);
            *(float4*)&attnW[base + 64 + tx * 4] = make_float4(s[i][4], s[i][5], s[i][6], s[i][7]);
        }

        // online (m, l) update; 16 lanes (same ty) share each row
#pragma unroll
        for (int i = 0; i < 8; i++) {
            float tm = s[i][0];
#pragma unroll
            for (int j = 1; j < 8; j++) tm = fmaxf(tm, s[i][j]);
#pragma unroll
            for (int off = 8; off; off >>= 1)
                tm = fmaxf(tm, __shfl_xor_sync(0xffffffffu, tm, off, 16));
            float nm = fmaxf(m[i], tm);
            float ps = 0.f;
#pragma unroll
            for (int j = 0; j < 8; j++) ps += __expf(s[i][j] - nm);
#pragma unroll
            for (int off = 8; off; off >>= 1)
                ps += __shfl_xor_sync(0xffffffffu, ps, off, 16);
            l[i] = l[i] * __expf(m[i] - nm) + ps;
            m[i] = nm;
        }
    }

    if (tx == 0) {
        size_t base = (size_t)(b * NUM_HEADS + h) * SEQ + q0;
#pragma unroll
        for (int i = 0; i < 8; i++) {
            g_m[base + qr[i]] = m[i];
            g_l[base + qr[i]] = l[i];
        }
    }
}

// ---------------------------------------------------------------------------
// Attention pass 2: read raw scores, emit final softmax weights, accumulate
// P @ V into g_AO. P scattered q-major into smem in 32-wide k chunks; PV
// inner loop batches 4 kk per step (12 LDS.128 per 128 FFMA).
// ---------------------------------------------------------------------------
__global__ __launch_bounds__(256)
void attn_pass2_kernel(float* __restrict__ attnW)
{
    const int qt  = blockIdx.x;
    const int h   = blockIdx.y;
    const int b   = blockIdx.z;
    const int tid = threadIdx.x;
    const int tx  = tid & 15;
    const int ty  = tid >> 4;

    __shared__ float smP[128][36];  // [q][k-chunk]  (stride 36: 144B rows)
    __shared__ float smV[32][68];   // [k][d]

    const int q0 = qt * 128;

    int qr[8];
#pragma unroll
    for (int i = 0; i < 8; i++)
        qr[i] = (i < 4) ? (ty * 4 + i) : (64 + ty * 4 + (i - 4));

    const size_t mlBase = (size_t)(b * NUM_HEADS + h) * SEQ + q0;
    float m[8], linv[8];
#pragma unroll
    for (int i = 0; i < 8; i++) {
        m[i]    = g_m[mlBase + qr[i]];
        linv[i] = 1.0f / g_l[mlBase + qr[i]];
    }

    float o[8][4];
#pragma unroll
    for (int i = 0; i < 8; i++)
#pragma unroll
        for (int j = 0; j < 4; j++) o[i][j] = 0.f;

    const size_t attnRowBase = (size_t)(b * NUM_HEADS + h) * SEQ + q0;

    for (int ks = 0; ks < SEQ; ks += 128) {
        // read raw scores, exponentiate, write final weights
        float p[8][8];
#pragma unroll
        for (int i = 0; i < 8; i++) {
            size_t base = (attnRowBase + qr[i]) * SEQ + ks;
            float4 s0 = *(const float4*)&attnW[base + tx * 4];
            float4 s1 = *(const float4*)&attnW[base + 64 + tx * 4];
            p[i][0] = __expf(s0.x - m[i]) * linv[i];
            p[i][1] = __expf(s0.y - m[i]) * linv[i];
            p[i][2] = __expf(s0.z - m[i]) * linv[i];
            p[i][3] = __expf(s0.w - m[i]) * linv[i];
            p[i][4] = __expf(s1.x - m[i]) * linv[i];
            p[i][5] = __expf(s1.y - m[i]) * linv[i];
            p[i][6] = __expf(s1.z - m[i]) * linv[i];
            p[i][7] = __expf(s1.w - m[i]) * linv[i];
            *(float4*)&attnW[base + tx * 4]      = make_float4(p[i][0], p[i][1], p[i][2], p[i][3]);
            *(float4*)&attnW[base + 64 + tx * 4] = make_float4(p[i][4], p[i][5], p[i][6], p[i][7]);
        }

        // P @ V over four 32-wide k chunks
#pragma unroll
        for (int c = 0; c < 4; c++) {
            const int cc = c & 1;          // which tx half owns this chunk
            const int jb = (c >> 1) * 4;   // p column group
            __syncthreads();
            if ((tx >> 3) == cc) {
                int col = (tx & 7) * 4;    // 0..28 within chunk
#pragma unroll
                for (int i = 0; i < 8; i++)
                    *(float4*)&smP[qr[i]][col] =
                        make_float4(p[i][jb + 0], p[i][jb + 1], p[i][jb + 2], p[i][jb + 3]);
            }
            // load V chunk [32][64]
#pragma unroll
            for (int u = 0; u < 2; u++) {
                int lin = tid + u * 256;
                int r   = lin >> 4;          // 0..31
                int d4  = (lin & 15) * 4;    // 0..60
                *(float4*)&smV[r][d4] =
                    *(const float4*)&g_V[(size_t)(b * SEQ + ks + c * 32 + r) * D_MODEL
                                         + h * HEAD_DIM + d4];
            }
            __syncthreads();

#pragma unroll
            for (int kb = 0; kb < 8; kb++) {
                float4 av[8];
#pragma unroll
                for (int i = 0; i < 8; i++)
                    av[i] = *(const float4*)&smP[qr[i]][kb * 4];
                float4 bv0 = *(const float4*)&smV[kb * 4 + 0][tx * 4];
                float4 bv1 = *(const float4*)&smV[kb * 4 + 1][tx * 4];
                float4 bv2 = *(const float4*)&smV[kb * 4 + 2][tx * 4];
                float4 bv3 = *(const float4*)&smV[kb * 4 + 3][tx * 4];
#pragma unroll
                for (int i = 0; i < 8; i++) {
                    o[i][0] = fmaf(av[i].x, bv0.x, o[i][0]);
                    o[i][1] = fmaf(av[i].x, bv0.y, o[i][1]);
                    o[i][2] = fmaf(av[i].x, bv0.z, o[i][2]);
                    o[i][3] = fmaf(av[i].x, bv0.w, o[i][3]);
                    o[i][0] = fmaf(av[i].y, bv1.x, o[i][0]);
                    o[i][1] = fmaf(av[i].y, bv1.y, o[i][1]);
                    o[i][2] = fmaf(av[i].y, bv1.z, o[i][2]);
                    o[i][3] = fmaf(av[i].y, bv1.w, o[i][3]);
                    o[i][0] = fmaf(av[i].z, bv2.x, o[i][0]);
                    o[i][1] = fmaf(av[i].z, bv2.y, o[i][1]);
                    o[i][2] = fmaf(av[i].z, bv2.z, o[i][2]);
                    o[i][3] = fmaf(av[i].z, bv2.w, o[i][3]);
                    o[i][0] = fmaf(av[i].w, bv3.x, o[i][0]);
                    o[i][1] = fmaf(av[i].w, bv3.y, o[i][1]);
                    o[i][2] = fmaf(av[i].w, bv3.z, o[i][2]);
                    o[i][3] = fmaf(av[i].w, bv3.w, o[i][3]);
                }
            }
        }
    }

    // attn_out in [B,S,H*Dh] layout -> ready for the O projection GEMM
#pragma unroll
    for (int i = 0; i < 8; i++) {
        size_t idx = (size_t)(b * SEQ + q0 + qr[i]) * D_MODEL + h * HEAD_DIM + tx * 4;
        *(float4*)&g_AO[idx] = make_float4(o[i][0], o[i][1], o[i][2], o[i][3]);
    }
}

// ---------------------------------------------------------------------------
// Launch: QKV projections -> attention (2 passes) -> output projection.
// Output layout: [output (B,S,D)] ++ [attn_weights (B,H,S,S)], fp32.
// ---------------------------------------------------------------------------
extern "C" void kernel_launch(void* const* d_in, const int* in_sizes, int n_in,
                              void* d_out, int out_size)
{
    const float* x  = (const float*)d_in[0];
    const int*   am = (const int*)  d_in[1];
    const float* Wq = (const float*)d_in[2];
    const float* bq = (const float*)d_in[3];
    const float* Wk = (const float*)d_in[4];
    const float* bk = (const float*)d_in[5];
    const float* Wv = (const float*)d_in[6];
    const float* bv = (const float*)d_in[7];
    const float* Wo = (const float*)d_in[8];
    const float* bo = (const float*)d_in[9];

    float* out   = (float*)d_out;
    float* attnW = out + (size_t)NROWS * D_MODEL;

    dim3 gGemm(D_MODEL / 128, NROWS / 128);   // (8, 32)

    sgemm_bias_kernel<<<gGemm, 256>>>(x, -1, Wq, bq, nullptr, 0,
                                      NROWS, D_MODEL, D_MODEL);
    sgemm_bias_kernel<<<gGemm, 256>>>(x, -1, Wk, bk, nullptr, 1,
                                      NROWS, D_MODEL, D_MODEL);
    sgemm_bias_kernel<<<gGemm, 256>>>(x, -1, Wv, bv, nullptr, 2,
                                      NROWS, D_MODEL, D_MODEL);

    dim3 gAttn(SEQ / 128, NUM_HEADS, BATCH);  // (16, 16, 2)
    attn_pass1_kernel<<<gAttn, 256>>>(am, attnW);
    attn_pass2_kernel<<<gAttn, 256>>>(attnW);

    sgemm_bias_kernel<<<gGemm, 256>>>(nullptr, 3, Wo, bo, out, -1,
                                      NROWS, D_MODEL, D_MODEL);
}

// round 8
// speedup vs baseline: 1.3758x; 1.3758x over previous
#include <cuda_runtime.h>
#include <cuda_bf16.h>
#include <cstdint>
#include <math.h>

#define D_MODEL   1024
#define NUM_HEADS 16
#define HEAD_DIM  64
#define BATCH     2
#define SEQ       2048
#define NROWS     (BATCH * SEQ)   // 4096

// ---------------------------------------------------------------------------
// Scratch (device globals; no runtime allocation allowed)
// ---------------------------------------------------------------------------
__device__ float g_Q [(size_t)NROWS * D_MODEL];
__device__ float g_K [(size_t)NROWS * D_MODEL];
__device__ float g_V [(size_t)NROWS * D_MODEL];
__device__ float g_AO[(size_t)NROWS * D_MODEL];
__device__ __nv_bfloat16 g_xh[(size_t)NROWS * D_MODEL];
__device__ __nv_bfloat16 g_xl[(size_t)NROWS * D_MODEL];
__device__ __nv_bfloat16 g_wh[(size_t)D_MODEL * D_MODEL];
__device__ __nv_bfloat16 g_wl[(size_t)D_MODEL * D_MODEL];

__device__ __forceinline__ float* scratch_ptr(int sel) {
    switch (sel) {
        case 0: return g_Q;
        case 1: return g_K;
        case 2: return g_V;
        default: return g_AO;
    }
}

// ---------------------------------------------------------------------------
// HMMA helpers (mma.sync bf16, supported on base sm_103 target)
// ---------------------------------------------------------------------------
__device__ __forceinline__ uint32_t smem_u32(const void* p) {
    uint32_t a;
    asm("{ .reg .u64 t; cvta.to.shared.u64 t, %1; cvt.u32.u64 %0, t; }"
        : "=r"(a) : "l"(p));
    return a;
}

__device__ __forceinline__ void ldmatrix_x4(uint32_t& r0, uint32_t& r1,
                                            uint32_t& r2, uint32_t& r3,
                                            uint32_t addr) {
    asm volatile("ldmatrix.sync.aligned.m8n8.x4.shared.b16 {%0,%1,%2,%3}, [%4];"
                 : "=r"(r0), "=r"(r1), "=r"(r2), "=r"(r3) : "r"(addr));
}
__device__ __forceinline__ void ldmatrix_x2(uint32_t& r0, uint32_t& r1,
                                            uint32_t addr) {
    asm volatile("ldmatrix.sync.aligned.m8n8.x2.shared.b16 {%0,%1}, [%2];"
                 : "=r"(r0), "=r"(r1) : "r"(addr));
}
__device__ __forceinline__ void mma_bf16(float* d, const uint32_t* a,
                                         const uint32_t* b) {
    asm volatile(
        "mma.sync.aligned.m16n8k16.row.col.f32.bf16.bf16.f32 "
        "{%0,%1,%2,%3}, {%4,%5,%6,%7}, {%8,%9}, {%0,%1,%2,%3};"
        : "+f"(d[0]), "+f"(d[1]), "+f"(d[2]), "+f"(d[3])
        : "r"(a[0]), "r"(a[1]), "r"(a[2]), "r"(a[3]), "r"(b[0]), "r"(b[1]));
}

// ---------------------------------------------------------------------------
// Split fp32 -> (hi, lo) bf16 pair. sel=-1 uses src pointer; sel>=0 scratch.
// ---------------------------------------------------------------------------
__global__ __launch_bounds__(256)
void split_kernel(const float* src, int sel)
{
    const float* A = (sel >= 0) ? scratch_ptr(sel) : src;
    size_t i4 = ((size_t)blockIdx.x * 256 + threadIdx.x) * 4;
    float4 v = *(const float4*)&A[i4];
    float vs[4] = {v.x, v.y, v.z, v.w};
    __nv_bfloat16 h[4], l[4];
#pragma unroll
    for (int j = 0; j < 4; j++) {
        h[j] = __float2bfloat16(vs[j]);
        l[j] = __float2bfloat16(vs[j] - __bfloat162float(h[j]));
    }
    __nv_bfloat162 h0 = {h[0], h[1]}, h1 = {h[2], h[3]};
    __nv_bfloat162 l0 = {l[0], l[1]}, l1 = {l[2], l[3]};
    uint2 uh, ul;
    uh.x = *(uint32_t*)&h0; uh.y = *(uint32_t*)&h1;
    ul.x = *(uint32_t*)&l0; ul.y = *(uint32_t*)&l1;
    *(uint2*)&g_xh[i4] = uh;
    *(uint2*)&g_xl[i4] = ul;
}

// ---------------------------------------------------------------------------
// W [K,N] fp32 -> transposed (hi, lo) bf16 [N,K] (K-major for HMMA B operand)
// ---------------------------------------------------------------------------
__global__ __launch_bounds__(256)
void wsplit_kernel(const float* __restrict__ W)
{
    __shared__ float ts[32][33];
    const int tx = threadIdx.x & 31, ty = threadIdx.x >> 5;
    const int n0 = blockIdx.x * 32, k0 = blockIdx.y * 32;
#pragma unroll
    for (int i = 0; i < 4; i++)
        ts[ty + i * 8][tx] = W[(size_t)(k0 + ty + i * 8) * D_MODEL + n0 + tx];
    __syncthreads();
#pragma unroll
    for (int i = 0; i < 4; i++) {
        float a = ts[tx][ty + i * 8];
        __nv_bfloat16 h = __float2bfloat16(a);
        __nv_bfloat16 l = __float2bfloat16(a - __bfloat162float(h));
        size_t o = (size_t)(n0 + ty + i * 8) * D_MODEL + k0 + tx;
        g_wh[o] = h; g_wl[o] = l;
    }
}

// ---------------------------------------------------------------------------
// HMMA bf16x3 GEMM: C[4096,1024] = A @ W + bias (fp32-class accuracy).
// A = (g_xh, g_xl) [M,K]; B = (g_wh, g_wl) [N,K], both K-major.
// 128x128 CTA tile, 8 warps (2 m x 4 n), 64x32 per warp, K-chunks of 32.
// Terms: Ah*Bh + Al*Bh + Ah*Bl accumulated in one fp32 chain.
// ---------------------------------------------------------------------------
#define KC 32
#define NCHUNK (D_MODEL / KC)   // 32
#define SSTRIDE 40              // bf16 units; 80B rows, conflict-free ldmatrix

__global__ __launch_bounds__(256)
void tc_gemm_kernel(const float* __restrict__ bias, float* C, int cSel)
{
    __shared__ __nv_bfloat16 sAh[128][SSTRIDE];
    __shared__ __nv_bfloat16 sAl[128][SSTRIDE];
    __shared__ __nv_bfloat16 sBh[128][SSTRIDE];
    __shared__ __nv_bfloat16 sBl[128][SSTRIDE];

    if (cSel >= 0) C = scratch_ptr(cSel);

    const int tid  = threadIdx.x;
    const int wid  = tid >> 5;
    const int lane = tid & 31;
    const int wm   = (wid & 1) * 64;    // warp m offset
    const int wn   = (wid >> 1) * 32;   // warp n offset

    const int bn = blockIdx.x * 128;
    const int bm = blockIdx.y * 128;

    float acc[4][4][4];
#pragma unroll
    for (int i = 0; i < 4; i++)
#pragma unroll
        for (int j = 0; j < 4; j++)
#pragma unroll
            for (int t = 0; t < 4; t++) acc[i][j][t] = 0.f;

    // loader indices: per operand 128 rows x 32 bf16 = 512 x 16B; 2 per thread
    const int ldRow = tid >> 2;          // 0..63 (+64 for u=1)
    const int ldSeg = tid & 3;           // 16B segment within row

    // ldmatrix base addresses (byte offsets within smem arrays)
    const uint32_t aAh = smem_u32(sAh), aAl = smem_u32(sAl);
    const uint32_t aBh = smem_u32(sBh), aBl = smem_u32(sBl);
    const int aRow = wm + (lane & 15);            // A fragment row
    const int aKh  = (lane >> 4);                 // A k-half (0/1)
    const int bRow = wn + (lane & 7);             // B fragment row base
    const int bKh  = (lane >> 3) & 1;             // B k-half (0/1)

    for (int c = 0; c < NCHUNK; c++) {
        const int k0 = c * KC;
        __syncthreads();
#pragma unroll
        for (int u = 0; u < 2; u++) {
            const int r = ldRow + u * 64;
            const size_t gA = (size_t)(bm + r) * D_MODEL + k0 + ldSeg * 8;
            const size_t gB = (size_t)(bn + r) * D_MODEL + k0 + ldSeg * 8;
            *(uint4*)&sAh[r][ldSeg * 8] = *(const uint4*)&g_xh[gA];
            *(uint4*)&sAl[r][ldSeg * 8] = *(const uint4*)&g_xl[gA];
            *(uint4*)&sBh[r][ldSeg * 8] = *(const uint4*)&g_wh[gB];
            *(uint4*)&sBl[r][ldSeg * 8] = *(const uint4*)&g_wl[gB];
        }
        __syncthreads();

#pragma unroll
        for (int step = 0; step < 2; step++) {
            const uint32_t kByteA = (uint32_t)(step * 32 + aKh * 16);
            const uint32_t kByteB = (uint32_t)(step * 32 + bKh * 16);

            uint32_t Bh[4][2], Bl[4][2];
#pragma unroll
            for (int nt = 0; nt < 4; nt++) {
                uint32_t off = (uint32_t)(bRow + nt * 8) * (SSTRIDE * 2) + kByteB;
                ldmatrix_x2(Bh[nt][0], Bh[nt][1], aBh + off);
                ldmatrix_x2(Bl[nt][0], Bl[nt][1], aBl + off);
            }
#pragma unroll
            for (int mt = 0; mt < 4; mt++) {
                uint32_t off = (uint32_t)(aRow + mt * 16) * (SSTRIDE * 2) + kByteA;
                uint32_t Ah[4], Al[4];
                ldmatrix_x4(Ah[0], Ah[1], Ah[2], Ah[3], aAh + off);
                ldmatrix_x4(Al[0], Al[1], Al[2], Al[3], aAl + off);
#pragma unroll
                for (int nt = 0; nt < 4; nt++) {
                    mma_bf16(acc[mt][nt], Ah, Bh[nt]);
                    mma_bf16(acc[mt][nt], Al, Bh[nt]);
                    mma_bf16(acc[mt][nt], Ah, Bl[nt]);
                }
            }
        }
    }

    // epilogue: fragment -> gmem with bias (float2 stores)
    const int cg = lane >> 2;        // fragment row group 0..7
    const int ct = (lane & 3) * 2;   // fragment col pair
#pragma unroll
    for (int mt = 0; mt < 4; mt++) {
#pragma unroll
        for (int nt = 0; nt < 4; nt++) {
            const int col = bn + wn + nt * 8 + ct;
            const float2 bv = *(const float2*)&bias[col];
            const int r0 = bm + wm + mt * 16 + cg;
            float2 v0 = {acc[mt][nt][0] + bv.x, acc[mt][nt][1] + bv.y};
            float2 v1 = {acc[mt][nt][2] + bv.x, acc[mt][nt][3] + bv.y};
            *(float2*)&C[(size_t)r0 * D_MODEL + col]       = v0;
            *(float2*)&C[(size_t)(r0 + 8) * D_MODEL + col] = v1;
        }
    }
}

// ---------------------------------------------------------------------------
// Attention per (b, h, 64-row Q tile): proven round-2 kernel (fp32).
// ---------------------------------------------------------------------------
__global__ __launch_bounds__(256)
void attn_kernel(const int* __restrict__ mask, float* __restrict__ attnW)
{
    const int qt  = blockIdx.x;
    const int h   = blockIdx.y;
    const int b   = blockIdx.z;
    const int tid = threadIdx.x;
    const int tx  = tid & 15;
    const int ty  = tid >> 4;

    __shared__ float smA[64][68];
    __shared__ float smB[64][68];
    __shared__ int   maskS[64];

    const int q0   = qt * 64;
    const int ldr  = tid >> 4;
    const int ldc4 = (tid & 15) * 4;

#pragma unroll
    for (int i = 0; i < 4; i++) {
        int q = ldr + i * 16;
        float4 v = *(const float4*)&g_Q[(size_t)(b * SEQ + q0 + q) * D_MODEL
                                        + h * HEAD_DIM + ldc4];
        smA[ldc4 + 0][q] = v.x; smA[ldc4 + 1][q] = v.y;
        smA[ldc4 + 2][q] = v.z; smA[ldc4 + 3][q] = v.w;
    }

    float m[4], l[4];
#pragma unroll
    for (int i = 0; i < 4; i++) { m[i] = -3.0e38f; l[i] = 0.f; }

    const size_t attnRowBase = (size_t)(b * NUM_HEADS + h) * SEQ + q0;

    for (int ks = 0; ks < SEQ; ks += 64) {
        __syncthreads();
#pragma unroll
        for (int i = 0; i < 4; i++) {
            int k = ldr + i * 16;
            float4 v = *(const float4*)&g_K[(size_t)(b * SEQ + ks + k) * D_MODEL
                                            + h * HEAD_DIM + ldc4];
            smB[ldc4 + 0][k] = v.x; smB[ldc4 + 1][k] = v.y;
            smB[ldc4 + 2][k] = v.z; smB[ldc4 + 3][k] = v.w;
        }
        if (tid < 64) maskS[tid] = mask[b * SEQ + ks + tid];
        __syncthreads();

        float s[4][4];
#pragma unroll
        for (int i = 0; i < 4; i++)
#pragma unroll
            for (int j = 0; j < 4; j++) s[i][j] = 0.f;

#pragma unroll 8
        for (int kk = 0; kk < 64; kk++) {
            float4 a  = *(const float4*)&smA[kk][ty * 4];
            float4 bb = *(const float4*)&smB[kk][tx * 4];
            float ar[4] = {a.x, a.y, a.z, a.w};
            float br[4] = {bb.x, bb.y, bb.z, bb.w};
#pragma unroll
            for (int i = 0; i < 4; i++)
#pragma unroll
                for (int j = 0; j < 4; j++)
                    s[i][j] = fmaf(ar[i], br[j], s[i][j]);
        }

#pragma unroll
        for (int j = 0; j < 4; j++) {
            bool masked = (maskS[tx * 4 + j] == 0);
#pragma unroll
            for (int i = 0; i < 4; i++) {
                float sv = s[i][j] * 0.125f;
                s[i][j] = masked ? -3.0e38f : sv;
            }
        }

#pragma unroll
        for (int i = 0; i < 4; i++) {
            size_t idx = (attnRowBase + ty * 4 + i) * SEQ + ks + tx * 4;
            *(float4*)&attnW[idx] = make_float4(s[i][0], s[i][1], s[i][2], s[i][3]);
        }

#pragma unroll
        for (int i = 0; i < 4; i++) {
            float tm = fmaxf(fmaxf(s[i][0], s[i][1]), fmaxf(s[i][2], s[i][3]));
#pragma unroll
            for (int off = 8; off; off >>= 1)
                tm = fmaxf(tm, __shfl_xor_sync(0xffffffffu, tm, off, 16));
            float nm = fmaxf(m[i], tm);
            float ps = __expf(s[i][0] - nm) + __expf(s[i][1] - nm)
                     + __expf(s[i][2] - nm) + __expf(s[i][3] - nm);
#pragma unroll
            for (int off = 8; off; off >>= 1)
                ps += __shfl_xor_sync(0xffffffffu, ps, off, 16);
            l[i] = l[i] * __expf(m[i] - nm) + ps;
            m[i] = nm;
        }
    }

    float invl[4];
#pragma unroll
    for (int i = 0; i < 4; i++) invl[i] = 1.0f / l[i];

    float o[4][4];
#pragma unroll
    for (int i = 0; i < 4; i++)
#pragma unroll
        for (int j = 0; j < 4; j++) o[i][j] = 0.f;

    for (int ks = 0; ks < SEQ; ks += 64) {
        __syncthreads();
#pragma unroll
        for (int i = 0; i < 4; i++) {
            int k = ldr + i * 16;
            float4 v = *(const float4*)&g_V[(size_t)(b * SEQ + ks + k) * D_MODEL
                                            + h * HEAD_DIM + ldc4];
            *(float4*)&smB[k][ldc4] = v;
        }
#pragma unroll
        for (int i = 0; i < 4; i++) {
            size_t idx = (attnRowBase + ty * 4 + i) * SEQ + ks + tx * 4;
            float4 sv = *(const float4*)&attnW[idx];
            float4 p;
            p.x = __expf(sv.x - m[i]) * invl[i];
            p.y = __expf(sv.y - m[i]) * invl[i];
            p.z = __expf(sv.z - m[i]) * invl[i];
            p.w = __expf(sv.w - m[i]) * invl[i];
            *(float4*)&attnW[idx] = p;
            smA[tx * 4 + 0][ty * 4 + i] = p.x;
            smA[tx * 4 + 1][ty * 4 + i] = p.y;
            smA[tx * 4 + 2][ty * 4 + i] = p.z;
            smA[tx * 4 + 3][ty * 4 + i] = p.w;
        }
        __syncthreads();

#pragma unroll 8
        for (int kk = 0; kk < 64; kk++) {
            float4 a  = *(const float4*)&smA[kk][ty * 4];
            float4 bb = *(const float4*)&smB[kk][tx * 4];
            float ar[4] = {a.x, a.y, a.z, a.w};
            float br[4] = {bb.x, bb.y, bb.z, bb.w};
#pragma unroll
            for (int i = 0; i < 4; i++)
#pragma unroll
                for (int j = 0; j < 4; j++)
                    o[i][j] = fmaf(ar[i], br[j], o[i][j]);
        }
    }

#pragma unroll
    for (int i = 0; i < 4; i++) {
        size_t idx = (size_t)(b * SEQ + q0 + ty * 4 + i) * D_MODEL
                   + h * HEAD_DIM + tx * 4;
        *(float4*)&g_AO[idx] = make_float4(o[i][0], o[i][1], o[i][2], o[i][3]);
    }
}

// ---------------------------------------------------------------------------
// Launch: split x -> [convert W, HMMA GEMM] x3 -> attention ->
//         split AO -> convert Wo -> HMMA GEMM -> out.
// ---------------------------------------------------------------------------
extern "C" void kernel_launch(void* const* d_in, const int* in_sizes, int n_in,
                              void* d_out, int out_size)
{
    const float* x  = (const float*)d_in[0];
    const int*   am = (const int*)  d_in[1];
    const float* Wq = (const float*)d_in[2];
    const float* bq = (const float*)d_in[3];
    const float* Wk = (const float*)d_in[4];
    const float* bk = (const float*)d_in[5];
    const float* Wv = (const float*)d_in[6];
    const float* bv = (const float*)d_in[7];
    const float* Wo = (const float*)d_in[8];
    const float* bo = (const float*)d_in[9];

    float* out   = (float*)d_out;
    float* attnW = out + (size_t)NROWS * D_MODEL;

    dim3 gW(D_MODEL / 32, D_MODEL / 32);        // (32, 32)
    dim3 gG(D_MODEL / 128, NROWS / 128);        // (8, 32)
    const int splitBlocks = (NROWS * D_MODEL) / (256 * 4);   // 4096

    split_kernel<<<splitBlocks, 256>>>(x, -1);

    wsplit_kernel<<<gW, 256>>>(Wq);
    tc_gemm_kernel<<<gG, 256>>>(bq, nullptr, 0);
    wsplit_kernel<<<gW, 256>>>(Wk);
    tc_gemm_kernel<<<gG, 256>>>(bk, nullptr, 1);
    wsplit_kernel<<<gW, 256>>>(Wv);
    tc_gemm_kernel<<<gG, 256>>>(bv, nullptr, 2);

    dim3 gAttn(SEQ / 64, NUM_HEADS, BATCH);     // (32, 16, 2)
    attn_kernel<<<gAttn, 256>>>(am, attnW);

    split_kernel<<<splitBlocks, 256>>>(nullptr, 3);
    wsplit_kernel<<<gW, 256>>>(Wo);
    tc_gemm_kernel<<<gG, 256>>>(bo, out, -1);
}

// round 10
// speedup vs baseline: 1.9303x; 1.4031x over previous
#include <cuda_runtime.h>
#include <cuda_bf16.h>
#include <cstdint>
#include <math.h>

#define D_MODEL   1024
#define NUM_HEADS 16
#define HEAD_DIM  64
#define BATCH     2
#define SEQ       2048
#define NROWS     (BATCH * SEQ)   // 4096

// ---------------------------------------------------------------------------
// Scratch (device globals; no runtime allocation allowed)
// ---------------------------------------------------------------------------
__device__ float g_AO[(size_t)NROWS * D_MODEL];
__device__ __nv_bfloat16 g_xh[(size_t)NROWS * D_MODEL];
__device__ __nv_bfloat16 g_xl[(size_t)NROWS * D_MODEL];
__device__ __nv_bfloat16 g_wh[(size_t)D_MODEL * D_MODEL];
__device__ __nv_bfloat16 g_wl[(size_t)D_MODEL * D_MODEL];
__device__ __nv_bfloat16 g_Qh[(size_t)NROWS * D_MODEL];
__device__ __nv_bfloat16 g_Ql[(size_t)NROWS * D_MODEL];
__device__ __nv_bfloat16 g_Kh[(size_t)NROWS * D_MODEL];
__device__ __nv_bfloat16 g_Kl[(size_t)NROWS * D_MODEL];
__device__ __nv_bfloat16 g_Vh[(size_t)NROWS * D_MODEL];
__device__ __nv_bfloat16 g_Vl[(size_t)NROWS * D_MODEL];

// ---------------------------------------------------------------------------
// HMMA helpers (mma.sync bf16, base sm_103 target)
// ---------------------------------------------------------------------------
__device__ __forceinline__ uint32_t smem_u32(const void* p) {
    uint32_t a;
    asm("{ .reg .u64 t; cvta.to.shared.u64 t, %1; cvt.u32.u64 %0, t; }"
        : "=r"(a) : "l"(p));
    return a;
}
__device__ __forceinline__ void ldmatrix_x4(uint32_t& r0, uint32_t& r1,
                                            uint32_t& r2, uint32_t& r3,
                                            uint32_t addr) {
    asm volatile("ldmatrix.sync.aligned.m8n8.x4.shared.b16 {%0,%1,%2,%3}, [%4];"
                 : "=r"(r0), "=r"(r1), "=r"(r2), "=r"(r3) : "r"(addr));
}
__device__ __forceinline__ void ldmatrix_x2(uint32_t& r0, uint32_t& r1,
                                            uint32_t addr) {
    asm volatile("ldmatrix.sync.aligned.m8n8.x2.shared.b16 {%0,%1}, [%2];"
                 : "=r"(r0), "=r"(r1) : "r"(addr));
}
__device__ __forceinline__ void ldmatrix_x2_trans(uint32_t& r0, uint32_t& r1,
                                                  uint32_t addr) {
    asm volatile("ldmatrix.sync.aligned.m8n8.x2.trans.shared.b16 {%0,%1}, [%2];"
                 : "=r"(r0), "=r"(r1) : "r"(addr));
}
__device__ __forceinline__ void mma_bf16(float* d, const uint32_t* a,
                                         const uint32_t* b) {
    asm volatile(
        "mma.sync.aligned.m16n8k16.row.col.f32.bf16.bf16.f32 "
        "{%0,%1,%2,%3}, {%4,%5,%6,%7}, {%8,%9}, {%0,%1,%2,%3};"
        : "+f"(d[0]), "+f"(d[1]), "+f"(d[2]), "+f"(d[3])
        : "r"(a[0]), "r"(a[1]), "r"(a[2]), "r"(a[3]), "r"(b[0]), "r"(b[1]));
}
__device__ __forceinline__ void split_bf16(float v, __nv_bfloat16& h,
                                           __nv_bfloat16& l) {
    h = __float2bfloat16(v);
    l = __float2bfloat16(v - __bfloat162float(h));
}

// ---------------------------------------------------------------------------
// Split fp32 -> (hi, lo) bf16. sel=-1: src pointer (x); sel>=0: g_AO.
// ---------------------------------------------------------------------------
__global__ __launch_bounds__(256)
void split_kernel(const float* src, int sel)
{
    const float* A = (sel >= 0) ? g_AO : src;
    size_t i4 = ((size_t)blockIdx.x * 256 + threadIdx.x) * 4;
    float4 v = *(const float4*)&A[i4];
    float vs[4] = {v.x, v.y, v.z, v.w};
    __nv_bfloat16 h[4], l[4];
#pragma unroll
    for (int j = 0; j < 4; j++) split_bf16(vs[j], h[j], l[j]);
    __nv_bfloat162 h0 = {h[0], h[1]}, h1 = {h[2], h[3]};
    __nv_bfloat162 l0 = {l[0], l[1]}, l1 = {l[2], l[3]};
    uint2 uh, ul;
    uh.x = *(uint32_t*)&h0; uh.y = *(uint32_t*)&h1;
    ul.x = *(uint32_t*)&l0; ul.y = *(uint32_t*)&l1;
    *(uint2*)&g_xh[i4] = uh;
    *(uint2*)&g_xl[i4] = ul;
}

// ---------------------------------------------------------------------------
// W [K,N] fp32 -> transposed (hi, lo) bf16 [N,K]
// ---------------------------------------------------------------------------
__global__ __launch_bounds__(256)
void wsplit_kernel(const float* __restrict__ W)
{
    __shared__ float ts[32][33];
    const int tx = threadIdx.x & 31, ty = threadIdx.x >> 5;
    const int n0 = blockIdx.x * 32, k0 = blockIdx.y * 32;
#pragma unroll
    for (int i = 0; i < 4; i++)
        ts[ty + i * 8][tx] = W[(size_t)(k0 + ty + i * 8) * D_MODEL + n0 + tx];
    __syncthreads();
#pragma unroll
    for (int i = 0; i < 4; i++) {
        float a = ts[tx][ty + i * 8];
        __nv_bfloat16 h, l;
        split_bf16(a, h, l);
        size_t o = (size_t)(n0 + ty + i * 8) * D_MODEL + k0 + tx;
        g_wh[o] = h; g_wl[o] = l;
    }
}

// ---------------------------------------------------------------------------
// HMMA bf16x3 GEMM: C = A @ W + bias. cSel 0/1/2: write bf16 hi/lo pairs
// into (Qh,Ql)/(Kh,Kl)/(Vh,Vl); cSel=-1: fp32 into C.
// 128x128 CTA tile, 8 warps (2m x 4n), K-chunks of 32.
// ---------------------------------------------------------------------------
#define KC 32
#define NCHUNK (D_MODEL / KC)
#define SSTRIDE 40

__global__ __launch_bounds__(256)
void tc_gemm_kernel(const float* __restrict__ bias, float* C, int cSel)
{
    __shared__ __nv_bfloat16 sAh[128][SSTRIDE];
    __shared__ __nv_bfloat16 sAl[128][SSTRIDE];
    __shared__ __nv_bfloat16 sBh[128][SSTRIDE];
    __shared__ __nv_bfloat16 sBl[128][SSTRIDE];

    const int tid  = threadIdx.x;
    const int wid  = tid >> 5;
    const int lane = tid & 31;
    const int wm   = (wid & 1) * 64;
    const int wn   = (wid >> 1) * 32;

    const int bn = blockIdx.x * 128;
    const int bm = blockIdx.y * 128;

    float acc[4][4][4];
#pragma unroll
    for (int i = 0; i < 4; i++)
#pragma unroll
        for (int j = 0; j < 4; j++)
#pragma unroll
            for (int t = 0; t < 4; t++) acc[i][j][t] = 0.f;

    const int ldRow = tid >> 2;
    const int ldSeg = tid & 3;

    const uint32_t aAh = smem_u32(sAh), aAl = smem_u32(sAl);
    const uint32_t aBh = smem_u32(sBh), aBl = smem_u32(sBl);
    const int aRow = wm + (lane & 15);
    const int aKh  = (lane >> 4);
    const int bRow = wn + (lane & 7);
    const int bKh  = (lane >> 3) & 1;

    for (int c = 0; c < NCHUNK; c++) {
        const int k0 = c * KC;
        __syncthreads();
#pragma unroll
        for (int u = 0; u < 2; u++) {
            const int r = ldRow + u * 64;
            const size_t gA = (size_t)(bm + r) * D_MODEL + k0 + ldSeg * 8;
            const size_t gB = (size_t)(bn + r) * D_MODEL + k0 + ldSeg * 8;
            *(uint4*)&sAh[r][ldSeg * 8] = *(const uint4*)&g_xh[gA];
            *(uint4*)&sAl[r][ldSeg * 8] = *(const uint4*)&g_xl[gA];
            *(uint4*)&sBh[r][ldSeg * 8] = *(const uint4*)&g_wh[gB];
            *(uint4*)&sBl[r][ldSeg * 8] = *(const uint4*)&g_wl[gB];
        }
        __syncthreads();

#pragma unroll
        for (int step = 0; step < 2; step++) {
            const uint32_t kByteA = (uint32_t)(step * 32 + aKh * 16);
            const uint32_t kByteB = (uint32_t)(step * 32 + bKh * 16);

            uint32_t Bh[4][2], Bl[4][2];
#pragma unroll
            for (int nt = 0; nt < 4; nt++) {
                uint32_t off = (uint32_t)(bRow + nt * 8) * (SSTRIDE * 2) + kByteB;
                ldmatrix_x2(Bh[nt][0], Bh[nt][1], aBh + off);
                ldmatrix_x2(Bl[nt][0], Bl[nt][1], aBl + off);
            }
#pragma unroll
            for (int mt = 0; mt < 4; mt++) {
                uint32_t off = (uint32_t)(aRow + mt * 16) * (SSTRIDE * 2) + kByteA;
                uint32_t Ah[4], Al[4];
                ldmatrix_x4(Ah[0], Ah[1], Ah[2], Ah[3], aAh + off);
                ldmatrix_x4(Al[0], Al[1], Al[2], Al[3], aAl + off);
#pragma unroll
                for (int nt = 0; nt < 4; nt++) {
                    mma_bf16(acc[mt][nt], Ah, Bh[nt]);
                    mma_bf16(acc[mt][nt], Al, Bh[nt]);
                    mma_bf16(acc[mt][nt], Ah, Bl[nt]);
                }
            }
        }
    }

    __nv_bfloat16* dh = (cSel == 0) ? g_Qh : (cSel == 1) ? g_Kh : g_Vh;
    __nv_bfloat16* dl = (cSel == 0) ? g_Ql : (cSel == 1) ? g_Kl : g_Vl;

    const int cg = lane >> 2;
    const int ct = (lane & 3) * 2;
#pragma unroll
    for (int mt = 0; mt < 4; mt++) {
#pragma unroll
        for (int nt = 0; nt < 4; nt++) {
            const int col = bn + wn + nt * 8 + ct;
            const float2 bv = *(const float2*)&bias[col];
            const int r0 = bm + wm + mt * 16 + cg;
            float e[2][2] = {{acc[mt][nt][0] + bv.x, acc[mt][nt][1] + bv.y},
                             {acc[mt][nt][2] + bv.x, acc[mt][nt][3] + bv.y}};
            if (cSel < 0) {
                *(float2*)&C[(size_t)r0 * D_MODEL + col]       = *(float2*)e[0];
                *(float2*)&C[(size_t)(r0 + 8) * D_MODEL + col] = *(float2*)e[1];
            } else {
#pragma unroll
                for (int u = 0; u < 2; u++) {
                    __nv_bfloat16 h0, l0, h1, l1;
                    split_bf16(e[u][0], h0, l0);
                    split_bf16(e[u][1], h1, l1);
                    __nv_bfloat162 ph = {h0, h1}, pl = {l0, l1};
                    size_t o = (size_t)(r0 + u * 8) * D_MODEL + col;
                    *(__nv_bfloat162*)&dh[o] = ph;
                    *(__nv_bfloat162*)&dl[o] = pl;
                }
            }
        }
    }
}

// ---------------------------------------------------------------------------
// Attention phase 1: raw scores via HMMA. Per (64-q tile, h, b); loops over
// 64-k tiles. S = (Qh+Ql)(Kh+Kl)^T * 0.125, masked; fp32 -> attnW.
// 8 warps: 2m x 4n -> warp tile 32x16 (mt=2, nt=2).
// ---------------------------------------------------------------------------
#define ATS 72   // bf16 row stride (144B): conflict-free ldmatrix

__global__ __launch_bounds__(256)
void attn_score_kernel(const int* __restrict__ mask, float* __restrict__ attnW)
{
    __shared__ __nv_bfloat16 sQh[64][ATS], sQl[64][ATS];
    __shared__ __nv_bfloat16 sKh[64][ATS], sKl[64][ATS];
    __shared__ int maskS[64];

    const int qt = blockIdx.x, h = blockIdx.y, b = blockIdx.z;
    const int tid  = threadIdx.x;
    const int wid  = tid >> 5;
    const int lane = tid & 31;
    const int wm   = (wid & 1) * 32;
    const int wn   = (wid >> 1) * 16;
    const int q0   = qt * 64;

    const uint32_t aQh = smem_u32(sQh), aQl = smem_u32(sQl);
    const uint32_t aKh = smem_u32(sKh), aKl = smem_u32(sKl);

    // load Q tile (64 rows x 64 bf16 per operand)
    {
        const int r = tid >> 2, s8 = (tid & 3) * 8;
        const size_t g = (size_t)(b * SEQ + q0 + r) * D_MODEL + h * HEAD_DIM;
        *(uint4*)&sQh[r][s8]      = *(const uint4*)&g_Qh[g + s8];
        *(uint4*)&sQh[r][s8 + 32] = *(const uint4*)&g_Qh[g + s8 + 32];
        *(uint4*)&sQl[r][s8]      = *(const uint4*)&g_Ql[g + s8];
        *(uint4*)&sQl[r][s8 + 32] = *(const uint4*)&g_Ql[g + s8 + 32];
    }

    const size_t rowBase = (size_t)(b * NUM_HEADS + h) * SEQ + q0;

    for (int ks = 0; ks < SEQ; ks += 64) {
        __syncthreads();
        {
            const int r = tid >> 2, s8 = (tid & 3) * 8;
            const size_t g = (size_t)(b * SEQ + ks + r) * D_MODEL + h * HEAD_DIM;
            *(uint4*)&sKh[r][s8]      = *(const uint4*)&g_Kh[g + s8];
            *(uint4*)&sKh[r][s8 + 32] = *(const uint4*)&g_Kh[g + s8 + 32];
            *(uint4*)&sKl[r][s8]      = *(const uint4*)&g_Kl[g + s8];
            *(uint4*)&sKl[r][s8 + 32] = *(const uint4*)&g_Kl[g + s8 + 32];
            if (tid < 64) maskS[tid] = mask[b * SEQ + ks + tid];
        }
        __syncthreads();

        float acc[2][2][4];
#pragma unroll
        for (int i = 0; i < 2; i++)
#pragma unroll
            for (int j = 0; j < 2; j++)
#pragma unroll
                for (int t = 0; t < 4; t++) acc[i][j][t] = 0.f;

#pragma unroll
        for (int st = 0; st < 4; st++) {
            const uint32_t kbA = (uint32_t)(st * 32 + (lane >> 4) * 16);
            const uint32_t kbB = (uint32_t)(st * 32 + ((lane >> 3) & 1) * 16);
            uint32_t Bh[2][2], Bl[2][2];
#pragma unroll
            for (int nt = 0; nt < 2; nt++) {
                uint32_t off = (uint32_t)(wn + nt * 8 + (lane & 7)) * (ATS * 2) + kbB;
                ldmatrix_x2(Bh[nt][0], Bh[nt][1], aKh + off);
                ldmatrix_x2(Bl[nt][0], Bl[nt][1], aKl + off);
            }
#pragma unroll
            for (int mt = 0; mt < 2; mt++) {
                uint32_t off = (uint32_t)(wm + mt * 16 + (lane & 15)) * (ATS * 2) + kbA;
                uint32_t Ah[4], Al[4];
                ldmatrix_x4(Ah[0], Ah[1], Ah[2], Ah[3], aQh + off);
                ldmatrix_x4(Al[0], Al[1], Al[2], Al[3], aQl + off);
#pragma unroll
                for (int nt = 0; nt < 2; nt++) {
                    mma_bf16(acc[mt][nt], Ah, Bh[nt]);
                    mma_bf16(acc[mt][nt], Al, Bh[nt]);
                    mma_bf16(acc[mt][nt], Ah, Bl[nt]);
                }
            }
        }

        // write raw scores (scale + mask)
        const int cg = lane >> 2, ct = (lane & 3) * 2;
#pragma unroll
        for (int mt = 0; mt < 2; mt++) {
#pragma unroll
            for (int nt = 0; nt < 2; nt++) {
                const int col = wn + nt * 8 + ct;
                const bool m0 = (maskS[col] == 0), m1 = (maskS[col + 1] == 0);
#pragma unroll
                for (int u = 0; u < 2; u++) {
                    const int rq = wm + mt * 16 + cg + u * 8;
                    float2 v;
                    v.x = m0 ? -3.0e38f : acc[mt][nt][u * 2 + 0] * 0.125f;
                    v.y = m1 ? -3.0e38f : acc[mt][nt][u * 2 + 1] * 0.125f;
                    *(float2*)&attnW[(rowBase + rq) * SEQ + ks + col] = v;
                }
            }
        }
    }
}

// ---------------------------------------------------------------------------
// Attention phase 2: row softmax in place. One block per row (65536 rows).
// ---------------------------------------------------------------------------
__global__ __launch_bounds__(256)
void softmax_kernel(float* __restrict__ attnW)
{
    __shared__ float red[8];
    const size_t row = blockIdx.x;
    float4* p = (float4*)(attnW + row * SEQ);
    const int tid = threadIdx.x;

    float4 v0 = p[tid], v1 = p[tid + 256];
    float vals[8] = {v0.x, v0.y, v0.z, v0.w, v1.x, v1.y, v1.z, v1.w};

    float mx = vals[0];
#pragma unroll
    for (int i = 1; i < 8; i++) mx = fmaxf(mx, vals[i]);
#pragma unroll
    for (int off = 16; off; off >>= 1)
        mx = fmaxf(mx, __shfl_xor_sync(0xffffffffu, mx, off));
    if ((tid & 31) == 0) red[tid >> 5] = mx;
    __syncthreads();
    mx = red[0];
#pragma unroll
    for (int i = 1; i < 8; i++) mx = fmaxf(mx, red[i]);
    __syncthreads();

    float e[8], s = 0.f;
#pragma unroll
    for (int i = 0; i < 8; i++) { e[i] = __expf(vals[i] - mx); s += e[i]; }
#pragma unroll
    for (int off = 16; off; off >>= 1)
        s += __shfl_xor_sync(0xffffffffu, s, off);
    if ((tid & 31) == 0) red[tid >> 5] = s;
    __syncthreads();
    s = red[0];
#pragma unroll
    for (int i = 1; i < 8; i++) s += red[i];

    const float inv = 1.0f / s;
    p[tid]       = make_float4(e[0] * inv, e[1] * inv, e[2] * inv, e[3] * inv);
    p[tid + 256] = make_float4(e[4] * inv, e[5] * inv, e[6] * inv, e[7] * inv);
}

// ---------------------------------------------------------------------------
// Attention phase 3: O = P @ V via HMMA. P read fp32 -> hi/lo bf16 smem;
// V col-operand via ldmatrix.trans on [k][d] smem. -> g_AO.
// ---------------------------------------------------------------------------
__global__ __launch_bounds__(256)
void attn_pv_kernel(const float* __restrict__ attnW)
{
    __shared__ __nv_bfloat16 sPh[64][ATS], sPl[64][ATS];
    __shared__ __nv_bfloat16 sVh[64][ATS], sVl[64][ATS];

    const int qt = blockIdx.x, h = blockIdx.y, b = blockIdx.z;
    const int tid  = threadIdx.x;
    const int wid  = tid >> 5;
    const int lane = tid & 31;
    const int wm   = (wid & 1) * 32;
    const int wn   = (wid >> 1) * 16;
    const int q0   = qt * 64;

    const uint32_t aPh = smem_u32(sPh), aPl = smem_u32(sPl);
    const uint32_t aVh = smem_u32(sVh), aVl = smem_u32(sVl);

    const size_t rowBase = (size_t)(b * NUM_HEADS + h) * SEQ + q0;

    float acc[2][2][4];
#pragma unroll
    for (int i = 0; i < 2; i++)
#pragma unroll
        for (int j = 0; j < 2; j++)
#pragma unroll
            for (int t = 0; t < 4; t++) acc[i][j][t] = 0.f;

    for (int ks = 0; ks < SEQ; ks += 64) {
        __syncthreads();
        // P tile: 64 rows x 64 cols fp32 -> hi/lo bf16
        {
            const int r = tid >> 2, cb = (tid & 3) * 16;
            const float* pr = attnW + (rowBase + r) * SEQ + ks + cb;
#pragma unroll
            for (int g = 0; g < 4; g++) {
                float4 f = *(const float4*)&pr[g * 4];
                __nv_bfloat16 h0, l0, h1, l1, h2, l2, h3, l3;
                split_bf16(f.x, h0, l0); split_bf16(f.y, h1, l1);
                split_bf16(f.z, h2, l2); split_bf16(f.w, h3, l3);
                __nv_bfloat162 ha = {h0, h1}, hb = {h2, h3};
                __nv_bfloat162 la = {l0, l1}, lb = {l2, l3};
                uint2 uh, ul;
                uh.x = *(uint32_t*)&ha; uh.y = *(uint32_t*)&hb;
                ul.x = *(uint32_t*)&la; ul.y = *(uint32_t*)&lb;
                *(uint2*)&sPh[r][cb + g * 4] = uh;
                *(uint2*)&sPl[r][cb + g * 4] = ul;
            }
        }
        // V tile: 64 k-rows x 64 d
        {
            const int r = tid >> 2, s8 = (tid & 3) * 8;
            const size_t g = (size_t)(b * SEQ + ks + r) * D_MODEL + h * HEAD_DIM;
            *(uint4*)&sVh[r][s8]      = *(const uint4*)&g_Vh[g + s8];
            *(uint4*)&sVh[r][s8 + 32] = *(const uint4*)&g_Vh[g + s8 + 32];
            *(uint4*)&sVl[r][s8]      = *(const uint4*)&g_Vl[g + s8];
            *(uint4*)&sVl[r][s8 + 32] = *(const uint4*)&g_Vl[g + s8 + 32];
        }
        __syncthreads();

#pragma unroll
        for (int st = 0; st < 4; st++) {
            const uint32_t kbA = (uint32_t)(st * 32 + (lane >> 4) * 16);
            // B (V^T) via trans: 16 k-rows x 8 d-cols per fragment
            uint32_t Bh[2][2], Bl[2][2];
#pragma unroll
            for (int nt = 0; nt < 2; nt++) {
                uint32_t off = (uint32_t)(st * 16 + (lane & 15)) * (ATS * 2)
                             + (uint32_t)(wn + nt * 8) * 2;
                ldmatrix_x2_trans(Bh[nt][0], Bh[nt][1], aVh + off);
                ldmatrix_x2_trans(Bl[nt][0], Bl[nt][1], aVl + off);
            }
#pragma unroll
            for (int mt = 0; mt < 2; mt++) {
                uint32_t off = (uint32_t)(wm + mt * 16 + (lane & 15)) * (ATS * 2) + kbA;
                uint32_t Ah[4], Al[4];
                ldmatrix_x4(Ah[0], Ah[1], Ah[2], Ah[3], aPh + off);
                ldmatrix_x4(Al[0], Al[1], Al[2], Al[3], aPl + off);
#pragma unroll
                for (int nt = 0; nt < 2; nt++) {
                    mma_bf16(acc[mt][nt], Ah, Bh[nt]);
                    mma_bf16(acc[mt][nt], Al, Bh[nt]);
                    mma_bf16(acc[mt][nt], Ah, Bl[nt]);
                }
            }
        }
    }

    // epilogue -> g_AO [B*S][D] (head-interleaved, ready for O projection)
    const int cg = lane >> 2, ct = (lane & 3) * 2;
#pragma unroll
    for (int mt = 0; mt < 2; mt++) {
#pragma unroll
        for (int nt = 0; nt < 2; nt++) {
            const int cd = wn + nt * 8 + ct;
#pragma unroll
            for (int u = 0; u < 2; u++) {
                const int rq = q0 + wm + mt * 16 + cg + u * 8;
                float2 v = {acc[mt][nt][u * 2 + 0], acc[mt][nt][u * 2 + 1]};
                *(float2*)&g_AO[(size_t)(b * SEQ + rq) * D_MODEL
                                + h * HEAD_DIM + cd] = v;
            }
        }
    }
}

// ---------------------------------------------------------------------------
// Launch
// ---------------------------------------------------------------------------
extern "C" void kernel_launch(void* const* d_in, const int* in_sizes, int n_in,
                              void* d_out, int out_size)
{
    const float* x  = (const float*)d_in[0];
    const int*   am = (const int*)  d_in[1];
    const float* Wq = (const float*)d_in[2];
    const float* bq = (const float*)d_in[3];
    const float* Wk = (const float*)d_in[4];
    const float* bk = (const float*)d_in[5];
    const float* Wv = (const float*)d_in[6];
    const float* bv = (const float*)d_in[7];
    const float* Wo = (const float*)d_in[8];
    const float* bo = (const float*)d_in[9];

    float* out   = (float*)d_out;
    float* attnW = out + (size_t)NROWS * D_MODEL;

    dim3 gW(D_MODEL / 32, D_MODEL / 32);
    dim3 gG(D_MODEL / 128, NROWS / 128);
    const int splitBlocks = (NROWS * D_MODEL) / (256 * 4);

    split_kernel<<<splitBlocks, 256>>>(x, -1);

    wsplit_kernel<<<gW, 256>>>(Wq);
    tc_gemm_kernel<<<gG, 256>>>(bq, nullptr, 0);
    wsplit_kernel<<<gW, 256>>>(Wk);
    tc_gemm_kernel<<<gG, 256>>>(bk, nullptr, 1);
    wsplit_kernel<<<gW, 256>>>(Wv);
    tc_gemm_kernel<<<gG, 256>>>(bv, nullptr, 2);

    dim3 gAttn(SEQ / 64, NUM_HEADS, BATCH);     // (32, 16, 2)
    attn_score_kernel<<<gAttn, 256>>>(am, attnW);
    softmax_kernel<<<(unsigned)(BATCH * NUM_HEADS * SEQ), 256>>>(attnW);
    attn_pv_kernel<<<gAttn, 256>>>(attnW);

    split_kernel<<<splitBlocks, 256>>>(nullptr, 3);
    wsplit_kernel<<<gW, 256>>>(Wo);
    tc_gemm_kernel<<<gG, 256>>>(bo, out, -1);
}

// round 12
// speedup vs baseline: 1.9636x; 1.0172x over previous
#include <cuda_runtime.h>
#include <cuda_bf16.h>
#include <cstdint>
#include <math.h>

#define D_MODEL   1024
#define NUM_HEADS 16
#define HEAD_DIM  64
#define BATCH     2
#define SEQ       2048
#define NROWS     (BATCH * SEQ)   // 4096
#define D2        ((size_t)D_MODEL * D_MODEL)

// ---------------------------------------------------------------------------
// Scratch (device globals; no runtime allocation allowed)
// ---------------------------------------------------------------------------
__device__ float g_AO[(size_t)NROWS * D_MODEL];
__device__ __nv_bfloat16 g_xh[(size_t)NROWS * D_MODEL];
__device__ __nv_bfloat16 g_xl[(size_t)NROWS * D_MODEL];
__device__ __nv_bfloat16 g_wh[3 * D2];
__device__ __nv_bfloat16 g_wl[3 * D2];
__device__ __nv_bfloat16 g_Qh[(size_t)NROWS * D_MODEL];
__device__ __nv_bfloat16 g_Ql[(size_t)NROWS * D_MODEL];
__device__ __nv_bfloat16 g_Kh[(size_t)NROWS * D_MODEL];
__device__ __nv_bfloat16 g_Kl[(size_t)NROWS * D_MODEL];
__device__ __nv_bfloat16 g_Vh[(size_t)NROWS * D_MODEL];
__device__ __nv_bfloat16 g_Vl[(size_t)NROWS * D_MODEL];
__device__ float g_m [(size_t)BATCH * NUM_HEADS * SEQ];
__device__ float g_il[(size_t)BATCH * NUM_HEADS * SEQ];

// ---------------------------------------------------------------------------
// HMMA helpers (mma.sync bf16, base sm_103 target)
// ---------------------------------------------------------------------------
__device__ __forceinline__ uint32_t smem_u32(const void* p) {
    uint32_t a;
    asm("{ .reg .u64 t; cvta.to.shared.u64 t, %1; cvt.u32.u64 %0, t; }"
        : "=r"(a) : "l"(p));
    return a;
}
__device__ __forceinline__ void ldmatrix_x4(uint32_t& r0, uint32_t& r1,
                                            uint32_t& r2, uint32_t& r3,
                                            uint32_t addr) {
    asm volatile("ldmatrix.sync.aligned.m8n8.x4.shared.b16 {%0,%1,%2,%3}, [%4];"
                 : "=r"(r0), "=r"(r1), "=r"(r2), "=r"(r3) : "r"(addr));
}
__device__ __forceinline__ void ldmatrix_x2(uint32_t& r0, uint32_t& r1,
                                            uint32_t addr) {
    asm volatile("ldmatrix.sync.aligned.m8n8.x2.shared.b16 {%0,%1}, [%2];"
                 : "=r"(r0), "=r"(r1) : "r"(addr));
}
__device__ __forceinline__ void ldmatrix_x2_trans(uint32_t& r0, uint32_t& r1,
                                                  uint32_t addr) {
    asm volatile("ldmatrix.sync.aligned.m8n8.x2.trans.shared.b16 {%0,%1}, [%2];"
                 : "=r"(r0), "=r"(r1) : "r"(addr));
}
__device__ __forceinline__ void mma_bf16(float* d, const uint32_t* a,
                                         const uint32_t* b) {
    asm volatile(
        "mma.sync.aligned.m16n8k16.row.col.f32.bf16.bf16.f32 "
        "{%0,%1,%2,%3}, {%4,%5,%6,%7}, {%8,%9}, {%0,%1,%2,%3};"
        : "+f"(d[0]), "+f"(d[1]), "+f"(d[2]), "+f"(d[3])
        : "r"(a[0]), "r"(a[1]), "r"(a[2]), "r"(a[3]), "r"(b[0]), "r"(b[1]));
}
__device__ __forceinline__ void split_bf16(float v, __nv_bfloat16& h,
                                           __nv_bfloat16& l) {
    h = __float2bfloat16(v);
    l = __float2bfloat16(v - __bfloat162float(h));
}

// ---------------------------------------------------------------------------
// Split fp32 -> (hi, lo) bf16. sel=-1: src pointer (x); sel>=0: g_AO.
// ---------------------------------------------------------------------------
__global__ __launch_bounds__(256)
void split_kernel(const float* src, int sel)
{
    const float* A = (sel >= 0) ? g_AO : src;
    size_t i4 = ((size_t)blockIdx.x * 256 + threadIdx.x) * 4;
    float4 v = *(const float4*)&A[i4];
    float vs[4] = {v.x, v.y, v.z, v.w};
    __nv_bfloat16 h[4], l[4];
#pragma unroll
    for (int j = 0; j < 4; j++) split_bf16(vs[j], h[j], l[j]);
    __nv_bfloat162 h0 = {h[0], h[1]}, h1 = {h[2], h[3]};
    __nv_bfloat162 l0 = {l[0], l[1]}, l1 = {l[2], l[3]};
    uint2 uh, ul;
    uh.x = *(uint32_t*)&h0; uh.y = *(uint32_t*)&h1;
    ul.x = *(uint32_t*)&l0; ul.y = *(uint32_t*)&l1;
    *(uint2*)&g_xh[i4] = uh;
    *(uint2*)&g_xl[i4] = ul;
}

// ---------------------------------------------------------------------------
// W [K,N] fp32 -> transposed (hi, lo) bf16 [N,K]; slot = blockIdx.z.
// ---------------------------------------------------------------------------
__global__ __launch_bounds__(256)
void wsplit_kernel(const float* w0, const float* w1, const float* w2)
{
    __shared__ float ts[32][33];
    const int z = blockIdx.z;
    const float* W = (z == 0) ? w0 : (z == 1) ? w1 : w2;
    __nv_bfloat16* dh = g_wh + (size_t)z * D2;
    __nv_bfloat16* dl = g_wl + (size_t)z * D2;
    const int tx = threadIdx.x & 31, ty = threadIdx.x >> 5;
    const int n0 = blockIdx.x * 32, k0 = blockIdx.y * 32;
#pragma unroll
    for (int i = 0; i < 4; i++)
        ts[ty + i * 8][tx] = W[(size_t)(k0 + ty + i * 8) * D_MODEL + n0 + tx];
    __syncthreads();
#pragma unroll
    for (int i = 0; i < 4; i++) {
        float a = ts[tx][ty + i * 8];
        __nv_bfloat16 h, l;
        split_bf16(a, h, l);
        size_t o = (size_t)(n0 + ty + i * 8) * D_MODEL + k0 + tx;
        dh[o] = h; dl[o] = l;
    }
}

// ---------------------------------------------------------------------------
// HMMA bf16x3 GEMM. qkvMode!=0: z=blockIdx.z selects weight slot z, bias z,
// and bf16 hi/lo destination (Q/K/V). qkvMode==0: weight slot 0, bias b0,
// fp32 output C.
// ---------------------------------------------------------------------------
#define KC 32
#define NCHUNK (D_MODEL / KC)
#define SSTRIDE 40

__global__ __launch_bounds__(256)
void tc_gemm_kernel(const float* __restrict__ b0, const float* __restrict__ b1,
                    const float* __restrict__ b2, float* C, int qkvMode)
{
    __shared__ __nv_bfloat16 sAh[128][SSTRIDE];
    __shared__ __nv_bfloat16 sAl[128][SSTRIDE];
    __shared__ __nv_bfloat16 sBh[128][SSTRIDE];
    __shared__ __nv_bfloat16 sBl[128][SSTRIDE];

    const int z = qkvMode ? blockIdx.z : 0;
    const float* bias = (z == 0) ? b0 : (z == 1) ? b1 : b2;
    const __nv_bfloat16* wh = g_wh + (size_t)z * D2;
    const __nv_bfloat16* wl = g_wl + (size_t)z * D2;

    const int tid  = threadIdx.x;
    const int wid  = tid >> 5;
    const int lane = tid & 31;
    const int wm   = (wid & 1) * 64;
    const int wn   = (wid >> 1) * 32;

    const int bn = blockIdx.x * 128;
    const int bm = blockIdx.y * 128;

    float acc[4][4][4];
#pragma unroll
    for (int i = 0; i < 4; i++)
#pragma unroll
        for (int j = 0; j < 4; j++)
#pragma unroll
            for (int t = 0; t < 4; t++) acc[i][j][t] = 0.f;

    const int ldRow = tid >> 2;
    const int ldSeg = tid & 3;

    const uint32_t aAh = smem_u32(sAh), aAl = smem_u32(sAl);
    const uint32_t aBh = smem_u32(sBh), aBl = smem_u32(sBl);
    const int aRow = wm + (lane & 15);
    const int aKh  = (lane >> 4);
    const int bRow = wn + (lane & 7);
    const int bKh  = (lane >> 3) & 1;

    for (int c = 0; c < NCHUNK; c++) {
        const int k0 = c * KC;
        __syncthreads();
#pragma unroll
        for (int u = 0; u < 2; u++) {
            const int r = ldRow + u * 64;
            const size_t gA = (size_t)(bm + r) * D_MODEL + k0 + ldSeg * 8;
            const size_t gB = (size_t)(bn + r) * D_MODEL + k0 + ldSeg * 8;
            *(uint4*)&sAh[r][ldSeg * 8] = *(const uint4*)&g_xh[gA];
            *(uint4*)&sAl[r][ldSeg * 8] = *(const uint4*)&g_xl[gA];
            *(uint4*)&sBh[r][ldSeg * 8] = *(const uint4*)&wh[gB];
            *(uint4*)&sBl[r][ldSeg * 8] = *(const uint4*)&wl[gB];
        }
        __syncthreads();

#pragma unroll
        for (int step = 0; step < 2; step++) {
            const uint32_t kByteA = (uint32_t)(step * 32 + aKh * 16);
            const uint32_t kByteB = (uint32_t)(step * 32 + bKh * 16);

            uint32_t Bh[4][2], Bl[4][2];
#pragma unroll
            for (int nt = 0; nt < 4; nt++) {
                uint32_t off = (uint32_t)(bRow + nt * 8) * (SSTRIDE * 2) + kByteB;
                ldmatrix_x2(Bh[nt][0], Bh[nt][1], aBh + off);
                ldmatrix_x2(Bl[nt][0], Bl[nt][1], aBl + off);
            }
#pragma unroll
            for (int mt = 0; mt < 4; mt++) {
                uint32_t off = (uint32_t)(aRow + mt * 16) * (SSTRIDE * 2) + kByteA;
                uint32_t Ah[4], Al[4];
                ldmatrix_x4(Ah[0], Ah[1], Ah[2], Ah[3], aAh + off);
                ldmatrix_x4(Al[0], Al[1], Al[2], Al[3], aAl + off);
#pragma unroll
                for (int nt = 0; nt < 4; nt++) {
                    mma_bf16(acc[mt][nt], Ah, Bh[nt]);
                    mma_bf16(acc[mt][nt], Al, Bh[nt]);
                    mma_bf16(acc[mt][nt], Ah, Bl[nt]);
                }
            }
        }
    }

    __nv_bfloat16* dh = (z == 0) ? g_Qh : (z == 1) ? g_Kh : g_Vh;
    __nv_bfloat16* dl = (z == 0) ? g_Ql : (z == 1) ? g_Kl : g_Vl;

    const int cg = lane >> 2;
    const int ct = (lane & 3) * 2;
#pragma unroll
    for (int mt = 0; mt < 4; mt++) {
#pragma unroll
        for (int nt = 0; nt < 4; nt++) {
            const int col = bn + wn + nt * 8 + ct;
            const float2 bv = *(const float2*)&bias[col];
            const int r0 = bm + wm + mt * 16 + cg;
            float e[2][2] = {{acc[mt][nt][0] + bv.x, acc[mt][nt][1] + bv.y},
                             {acc[mt][nt][2] + bv.x, acc[mt][nt][3] + bv.y}};
            if (!qkvMode) {
                *(float2*)&C[(size_t)r0 * D_MODEL + col]       = *(float2*)e[0];
                *(float2*)&C[(size_t)(r0 + 8) * D_MODEL + col] = *(float2*)e[1];
            } else {
#pragma unroll
                for (int u = 0; u < 2; u++) {
                    __nv_bfloat16 h0, l0, h1, l1;
                    split_bf16(e[u][0], h0, l0);
                    split_bf16(e[u][1], h1, l1);
                    __nv_bfloat162 ph = {h0, h1}, pl = {l0, l1};
                    size_t o = (size_t)(r0 + u * 8) * D_MODEL + col;
                    *(__nv_bfloat162*)&dh[o] = ph;
                    *(__nv_bfloat162*)&dl[o] = pl;
                }
            }
        }
    }
}

// ---------------------------------------------------------------------------
// Attention phase 1: raw scores via HMMA + exact online (m, l) per row.
// Writes raw scores to attnW (finalized in pv), row stats to g_m / g_il.
// Block = (64-q tile, h, b); 8 warps: 2m x 4n.
// ---------------------------------------------------------------------------
#define ATS 72   // bf16 row stride (144B): conflict-free ldmatrix

__global__ __launch_bounds__(256)
void attn_score_kernel(const int* __restrict__ mask, float* __restrict__ attnW)
{
    __shared__ __nv_bfloat16 sQh[64][ATS], sQl[64][ATS];
    __shared__ __nv_bfloat16 sKh[64][ATS], sKl[64][ATS];
    __shared__ int   maskS[64];
    __shared__ float sM[4][64], sL[4][64];

    const int qt = blockIdx.x, h = blockIdx.y, b = blockIdx.z;
    const int tid  = threadIdx.x;
    const int wid  = tid >> 5;
    const int lane = tid & 31;
    const int wm   = (wid & 1) * 32;
    const int wn   = (wid >> 1) * 16;
    const int q0   = qt * 64;

    const uint32_t aQh = smem_u32(sQh), aQl = smem_u32(sQl);
    const uint32_t aKh = smem_u32(sKh), aKl = smem_u32(sKl);

    {
        const int r = tid >> 2, s8 = (tid & 3) * 8;
        const size_t g = (size_t)(b * SEQ + q0 + r) * D_MODEL + h * HEAD_DIM;
        *(uint4*)&sQh[r][s8]      = *(const uint4*)&g_Qh[g + s8];
        *(uint4*)&sQh[r][s8 + 32] = *(const uint4*)&g_Qh[g + s8 + 32];
        *(uint4*)&sQl[r][s8]      = *(const uint4*)&g_Ql[g + s8];
        *(uint4*)&sQl[r][s8 + 32] = *(const uint4*)&g_Ql[g + s8 + 32];
    }

    const size_t rowBase = (size_t)(b * NUM_HEADS + h) * SEQ + q0;

    // online stats: one (m,l) per (mt,u) row owned by this lane's quad
    float rm[4], rl[4];
#pragma unroll
    for (int i = 0; i < 4; i++) { rm[i] = -3.0e38f; rl[i] = 0.f; }

    for (int ks = 0; ks < SEQ; ks += 64) {
        __syncthreads();
        {
            const int r = tid >> 2, s8 = (tid & 3) * 8;
            const size_t g = (size_t)(b * SEQ + ks + r) * D_MODEL + h * HEAD_DIM;
            *(uint4*)&sKh[r][s8]      = *(const uint4*)&g_Kh[g + s8];
            *(uint4*)&sKh[r][s8 + 32] = *(const uint4*)&g_Kh[g + s8 + 32];
            *(uint4*)&sKl[r][s8]      = *(const uint4*)&g_Kl[g + s8];
            *(uint4*)&sKl[r][s8 + 32] = *(const uint4*)&g_Kl[g + s8 + 32];
            if (tid < 64) maskS[tid] = mask[b * SEQ + ks + tid];
        }
        __syncthreads();

        float acc[2][2][4];
#pragma unroll
        for (int i = 0; i < 2; i++)
#pragma unroll
            for (int j = 0; j < 2; j++)
#pragma unroll
                for (int t = 0; t < 4; t++) acc[i][j][t] = 0.f;

#pragma unroll
        for (int st = 0; st < 4; st++) {
            const uint32_t kbA = (uint32_t)(st * 32 + (lane >> 4) * 16);
            const uint32_t kbB = (uint32_t)(st * 32 + ((lane >> 3) & 1) * 16);
            uint32_t Bh[2][2], Bl[2][2];
#pragma unroll
            for (int nt = 0; nt < 2; nt++) {
                uint32_t off = (uint32_t)(wn + nt * 8 + (lane & 7)) * (ATS * 2) + kbB;
                ldmatrix_x2(Bh[nt][0], Bh[nt][1], aKh + off);
                ldmatrix_x2(Bl[nt][0], Bl[nt][1], aKl + off);
            }
#pragma unroll
            for (int mt = 0; mt < 2; mt++) {
                uint32_t off = (uint32_t)(wm + mt * 16 + (lane & 15)) * (ATS * 2) + kbA;
                uint32_t Ah[4], Al[4];
                ldmatrix_x4(Ah[0], Ah[1], Ah[2], Ah[3], aQh + off);
                ldmatrix_x4(Al[0], Al[1], Al[2], Al[3], aQl + off);
#pragma unroll
                for (int nt = 0; nt < 2; nt++) {
                    mma_bf16(acc[mt][nt], Ah, Bh[nt]);
                    mma_bf16(acc[mt][nt], Al, Bh[nt]);
                    mma_bf16(acc[mt][nt], Ah, Bl[nt]);
                }
            }
        }

        // scale + mask, write raw scores, update online (m,l)
        const int cg = lane >> 2, ct = (lane & 3) * 2;
#pragma unroll
        for (int mt = 0; mt < 2; mt++) {
#pragma unroll
            for (int u = 0; u < 2; u++) {
                const int idx = mt * 2 + u;
                float v[4];   // this lane's 4 cols for row (mt,u)
#pragma unroll
                for (int nt = 0; nt < 2; nt++) {
                    const int col = wn + nt * 8 + ct;
                    const bool m0 = (maskS[col] == 0), m1 = (maskS[col + 1] == 0);
                    float a0 = m0 ? -3.0e38f : acc[mt][nt][u * 2 + 0] * 0.125f;
                    float a1 = m1 ? -3.0e38f : acc[mt][nt][u * 2 + 1] * 0.125f;
                    v[nt * 2 + 0] = a0; v[nt * 2 + 1] = a1;
                    const int rq = wm + mt * 16 + cg + u * 8;
                    *(float2*)&attnW[(rowBase + rq) * SEQ + ks + col] =
                        make_float2(a0, a1);
                }
                float tm = fmaxf(fmaxf(v[0], v[1]), fmaxf(v[2], v[3]));
                tm = fmaxf(tm, __shfl_xor_sync(0xffffffffu, tm, 1));
                tm = fmaxf(tm, __shfl_xor_sync(0xffffffffu, tm, 2));
                float nm = fmaxf(rm[idx], tm);
                float ps = __expf(v[0] - nm) + __expf(v[1] - nm)
                         + __expf(v[2] - nm) + __expf(v[3] - nm);
                ps += __shfl_xor_sync(0xffffffffu, ps, 1);
                ps += __shfl_xor_sync(0xffffffffu, ps, 2);
                rl[idx] = rl[idx] * __expf(rm[idx] - nm) + ps;
                rm[idx] = nm;
            }
        }
    }

    // cross-warp combine: 4 column-warp-groups per row set
    const int g = wid >> 1;
    if ((lane & 3) == 0) {
        const int cg = lane >> 2;
#pragma unroll
        for (int mt = 0; mt < 2; mt++)
#pragma unroll
            for (int u = 0; u < 2; u++) {
                const int r = wm + mt * 16 + cg + u * 8;
                sM[g][r] = rm[mt * 2 + u];
                sL[g][r] = rl[mt * 2 + u];
            }
    }
    __syncthreads();
    if (tid < 64) {
        float M = sM[0][tid];
#pragma unroll
        for (int gg = 1; gg < 4; gg++) M = fmaxf(M, sM[gg][tid]);
        float L = 0.f;
#pragma unroll
        for (int gg = 0; gg < 4; gg++)
            L += sL[gg][tid] * __expf(sM[gg][tid] - M);
        g_m [rowBase + tid] = M;
        g_il[rowBase + tid] = 1.0f / L;
    }
}

// ---------------------------------------------------------------------------
// Attention phase 2: read raw scores, finalize P in place (exp * invl),
// accumulate O = P @ V via HMMA -> g_AO.
// ---------------------------------------------------------------------------
__global__ __launch_bounds__(256)
void attn_pv_kernel(float* __restrict__ attnW)
{
    __shared__ __nv_bfloat16 sPh[64][ATS], sPl[64][ATS];
    __shared__ __nv_bfloat16 sVh[64][ATS], sVl[64][ATS];

    const int qt = blockIdx.x, h = blockIdx.y, b = blockIdx.z;
    const int tid  = threadIdx.x;
    const int wid  = tid >> 5;
    const int lane = tid & 31;
    const int wm   = (wid & 1) * 32;
    const int wn   = (wid >> 1) * 16;
    const int q0   = qt * 64;

    const uint32_t aPh = smem_u32(sPh), aPl = smem_u32(sPl);
    const uint32_t aVh = smem_u32(sVh), aVl = smem_u32(sVl);

    const size_t rowBase = (size_t)(b * NUM_HEADS + h) * SEQ + q0;

    // per-thread row stats for the P-tile rows this thread loads
    const int prow = tid >> 2;
    const float prM  = g_m [rowBase + prow];
    const float prIL = g_il[rowBase + prow];

    float acc[2][2][4];
#pragma unroll
    for (int i = 0; i < 2; i++)
#pragma unroll
        for (int j = 0; j < 2; j++)
#pragma unroll
            for (int t = 0; t < 4; t++) acc[i][j][t] = 0.f;

    for (int ks = 0; ks < SEQ; ks += 64) {
        __syncthreads();
        // P tile: raw fp32 -> exp*invl -> write back + hi/lo bf16 smem
        {
            const int cb = (tid & 3) * 16;
            float* pr = attnW + (rowBase + prow) * SEQ + ks + cb;
#pragma unroll
            for (int g = 0; g < 4; g++) {
                float4 f = *(const float4*)&pr[g * 4];
                f.x = __expf(f.x - prM) * prIL;
                f.y = __expf(f.y - prM) * prIL;
                f.z = __expf(f.z - prM) * prIL;
                f.w = __expf(f.w - prM) * prIL;
                *(float4*)&pr[g * 4] = f;
                __nv_bfloat16 h0, l0, h1, l1, h2, l2, h3, l3;
                split_bf16(f.x, h0, l0); split_bf16(f.y, h1, l1);
                split_bf16(f.z, h2, l2); split_bf16(f.w, h3, l3);
                __nv_bfloat162 ha = {h0, h1}, hb = {h2, h3};
                __nv_bfloat162 la = {l0, l1}, lb = {l2, l3};
                uint2 uh, ul;
                uh.x = *(uint32_t*)&ha; uh.y = *(uint32_t*)&hb;
                ul.x = *(uint32_t*)&la; ul.y = *(uint32_t*)&lb;
                *(uint2*)&sPh[prow][cb + g * 4] = uh;
                *(uint2*)&sPl[prow][cb + g * 4] = ul;
            }
        }
        // V tile: 64 k-rows x 64 d
        {
            const int r = tid >> 2, s8 = (tid & 3) * 8;
            const size_t g = (size_t)(b * SEQ + ks + r) * D_MODEL + h * HEAD_DIM;
            *(uint4*)&sVh[r][s8]      = *(const uint4*)&g_Vh[g + s8];
            *(uint4*)&sVh[r][s8 + 32] = *(const uint4*)&g_Vh[g + s8 + 32];
            *(uint4*)&sVl[r][s8]      = *(const uint4*)&g_Vl[g + s8];
            *(uint4*)&sVl[r][s8 + 32] = *(const uint4*)&g_Vl[g + s8 + 32];
        }
        __syncthreads();

#pragma unroll
        for (int st = 0; st < 4; st++) {
            const uint32_t kbA = (uint32_t)(st * 32 + (lane >> 4) * 16);
            uint32_t Bh[2][2], Bl[2][2];
#pragma unroll
            for (int nt = 0; nt < 2; nt++) {
                uint32_t off = (uint32_t)(st * 16 + (lane & 15)) * (ATS * 2)
                             + (uint32_t)(wn + nt * 8) * 2;
                ldmatrix_x2_trans(Bh[nt][0], Bh[nt][1], aVh + off);
                ldmatrix_x2_trans(Bl[nt][0], Bl[nt][1], aVl + off);
            }
#pragma unroll
            for (int mt = 0; mt < 2; mt++) {
                uint32_t off = (uint32_t)(wm + mt * 16 + (lane & 15)) * (ATS * 2) + kbA;
                uint32_t Ah[4], Al[4];
                ldmatrix_x4(Ah[0], Ah[1], Ah[2], Ah[3], aPh + off);
                ldmatrix_x4(Al[0], Al[1], Al[2], Al[3], aPl + off);
#pragma unroll
                for (int nt = 0; nt < 2; nt++) {
                    mma_bf16(acc[mt][nt], Ah, Bh[nt]);
                    mma_bf16(acc[mt][nt], Al, Bh[nt]);
                    mma_bf16(acc[mt][nt], Ah, Bl[nt]);
                }
            }
        }
    }

    const int cg = lane >> 2, ct = (lane & 3) * 2;
#pragma unroll
    for (int mt = 0; mt < 2; mt++) {
#pragma unroll
        for (int nt = 0; nt < 2; nt++) {
            const int cd = wn + nt * 8 + ct;
#pragma unroll
            for (int u = 0; u < 2; u++) {
                const int rq = q0 + wm + mt * 16 + cg + u * 8;
                float2 v = {acc[mt][nt][u * 2 + 0], acc[mt][nt][u * 2 + 1]};
                *(float2*)&g_AO[(size_t)(b * SEQ + rq) * D_MODEL
                                + h * HEAD_DIM + cd] = v;
            }
        }
    }
}

// ---------------------------------------------------------------------------
// Launch
// ---------------------------------------------------------------------------
extern "C" void kernel_launch(void* const* d_in, const int* in_sizes, int n_in,
                              void* d_out, int out_size)
{
    const float* x  = (const float*)d_in[0];
    const int*   am = (const int*)  d_in[1];
    const float* Wq = (const float*)d_in[2];
    const float* bq = (const float*)d_in[3];
    const float* Wk = (const float*)d_in[4];
    const float* bk = (const float*)d_in[5];
    const float* Wv = (const float*)d_in[6];
    const float* bv = (const float*)d_in[7];
    const float* Wo = (const float*)d_in[8];
    const float* bo = (const float*)d_in[9];

    float* out   = (float*)d_out;
    float* attnW = out + (size_t)NROWS * D_MODEL;

    const int splitBlocks = (NROWS * D_MODEL) / (256 * 4);

    split_kernel<<<splitBlocks, 256>>>(x, -1);

    dim3 gW3(D_MODEL / 32, D_MODEL / 32, 3);
    wsplit_kernel<<<gW3, 256>>>(Wq, Wk, Wv);
    dim3 gG3(D_MODEL / 128, NROWS / 128, 3);
    tc_gemm_kernel<<<gG3, 256>>>(bq, bk, bv, nullptr, 1);

    dim3 gAttn(SEQ / 64, NUM_HEADS, BATCH);     // (32, 16, 2)
    attn_score_kernel<<<gAttn, 256>>>(am, attnW);
    attn_pv_kernel<<<gAttn, 256>>>(attnW);

    split_kernel<<<splitBlocks, 256>>>(nullptr, 3);
    dim3 gW1(D_MODEL / 32, D_MODEL / 32, 1);
    wsplit_kernel<<<gW1, 256>>>(Wo, Wo, Wo);
    dim3 gG1(D_MODEL / 128, NROWS / 128, 1);
    tc_gemm_kernel<<<gG1, 256>>>(bo, bo, bo, out, 0);
}